// round 16
// baseline (speedup 1.0000x reference)
#include <cuda_runtime.h>
#include <cstdint>
#include <cstddef>

// Problem constants
#define B_  256
#define T_  1024
#define I_  8
#define H_  256
#define L_  32          // steps per chunk
#define C_  32          // number of chunks
#define BH  (B_*H_)
#define KU  512         // U width = H + L*I
#define NW  8192        // out-cols = L*H per chunk-col-space (32*256)

// ---------------- device scratch (no allocations allowed) ----------------
__device__ float    g_Pows[33 * H_ * H_];     // Pows[j] = (Wh^T)^j, j=1..32
__device__ float    g_Mstack[H_ * H_];        // row block (31-p)*8 = Wx^T A^p
__device__ uint32_t g_Ghi[KU * NW];           // G split to tf32 hi/lo
__device__ uint32_t g_Glo[KU * NW];
__device__ uint32_t g_Uhi[(size_t)8192 * KU]; // U split to tf32 hi/lo
__device__ uint32_t g_Ulo[(size_t)8192 * KU];
__device__ float    g_Zend[(size_t)C_ * BH];
__device__ float    g_Hstart[(size_t)C_ * BH];

// ---------------- helpers ----------------
__device__ __forceinline__ unsigned long long pack2(float v) {
    unsigned long long r;
    asm("mov.b64 %0, {%1, %1};" : "=l"(r) : "f"(v));
    return r;
}
__device__ __forceinline__ void fma2(unsigned long long& d,
                                     unsigned long long a,
                                     unsigned long long b) {
    asm("fma.rn.f32x2 %0, %1, %2, %0;" : "+l"(d) : "l"(a), "l"(b));
}
__device__ __forceinline__ void split_tf32(float v, uint32_t& hi, uint32_t& lo) {
    uint32_t h;
    asm("cvt.rna.tf32.f32 %0, %1;" : "=r"(h) : "f"(v));
    float hf = __uint_as_float(h);
    asm("cvt.rna.tf32.f32 %0, %1;" : "=r"(lo) : "f"(v - hf));
    hi = h;
}
__device__ __forceinline__ void mma_tf32(float (&d)[4], const uint32_t (&a)[4],
                                         uint32_t b0, uint32_t b1) {
    asm volatile(
        "mma.sync.aligned.m16n8k8.row.col.f32.tf32.tf32.f32 "
        "{%0,%1,%2,%3}, {%4,%5,%6,%7}, {%8,%9}, {%0,%1,%2,%3};"
        : "+f"(d[0]), "+f"(d[1]), "+f"(d[2]), "+f"(d[3])
        : "r"(a[0]), "r"(a[1]), "r"(a[2]), "r"(a[3]), "r"(b0), "r"(b1));
}

// ---------------- out[0] = broadcast h0 ----------------
__global__ void k_out0(float* __restrict__ out, const float* __restrict__ h0) {
    int idx = blockIdx.x * 256 + threadIdx.x;
    out[idx] = h0[idx & (H_ - 1)];
}

// ---- seed Pows[1] = Wh^T and Mstack V_0 = Wx^T ----
__global__ void k_prep(const float* __restrict__ Wh, const float* __restrict__ Wx) {
    int idx = blockIdx.x * 256 + threadIdx.x;       // 67584
    if (idx < H_ * H_) {
        int h = idx >> 8, c = idx & 255;
        g_Pows[H_ * H_ + idx] = Wh[c * H_ + h];     // (Wh^T)[h][c]
    } else if (idx < H_ * H_ + I_ * H_) {
        int r = idx - H_ * H_;
        int i = r >> 8, c = r & 255;
        g_Mstack[((L_ - 1) * I_ + i) * H_ + c] = Wx[c * I_ + i];
    }
}

// ---- power doubling: stage m: for kk=1..2^m: Pows[kk+2^m] = Pows[kk]@Pows[2^m]
__global__ void k_pow(int stage) {
    const int nk = 1 << stage;
    const int kk = blockIdx.z + 1;                  // 1..nk
    const float* src  = g_Pows + (size_t)kk * (H_ * H_);
    const float* mult = g_Pows + (size_t)nk * (H_ * H_);
    float* dst        = g_Pows + (size_t)(kk + nk) * (H_ * H_);
    __shared__ float as[32][33], bs[32][33];
    const int tx = threadIdx.x & 31;
    const int ty = threadIdx.x >> 5;
    const int row0 = blockIdx.y * 32, col0 = blockIdx.x * 32;
    float acc[4] = {0.f, 0.f, 0.f, 0.f};
    for (int k0 = 0; k0 < H_; k0 += 32) {
#pragma unroll
        for (int e = 0; e < 4; e++) {
            int r = ty + e * 8;
            as[r][tx] = src[(size_t)(row0 + r) * H_ + k0 + tx];
            bs[r][tx] = mult[(size_t)(k0 + r) * H_ + col0 + tx];
        }
        __syncthreads();
#pragma unroll
        for (int kq = 0; kq < 32; kq++) {
            float bv = bs[kq][tx];
#pragma unroll
            for (int e = 0; e < 4; e++) acc[e] += as[ty + e * 8][kq] * bv;
        }
        __syncthreads();
    }
#pragma unroll
    for (int e = 0; e < 4; e++)
        dst[(size_t)(row0 + ty + e * 8) * H_ + col0 + tx] = acc[e];
}

// ---- Mstack doubling: stage m: V_{k+2^m} = V_k @ Pows[2^m], k=0..2^m-1 ------
__global__ void __launch_bounds__(256, 1) k_vstage(int stage) {
    const int nk = 1 << stage;
    const float* P = g_Pows + (size_t)nk * (H_ * H_);
    const int k = blockIdx.x;
    const int c = threadIdx.x;
    __shared__ float V[I_][H_];
    const float* src = g_Mstack + (size_t)((L_ - 1 - k) * I_) * H_;
#pragma unroll
    for (int i = 0; i < I_; i++) V[i][c] = src[i * H_ + c];
    __syncthreads();
    float acc[I_] = {0.f, 0.f, 0.f, 0.f, 0.f, 0.f, 0.f, 0.f};
#pragma unroll 8
    for (int h = 0; h < H_; h++) {
        float a = P[h * H_ + c];
#pragma unroll
        for (int i = 0; i < I_; i++) acc[i] += V[i][h] * a;
    }
    float* dst = g_Mstack + (size_t)((L_ - 1 - k - nk) * I_) * H_;
#pragma unroll
    for (int i = 0; i < I_; i++) dst[i * H_ + c] = acc[i];
}

// ---- build G (512 x 8192) split to tf32 hi/lo ----
__global__ void k_buildG() {
    int idx = blockIdx.x * 256 + threadIdx.x;       // 4M
    int col = idx & (NW - 1);
    int r   = idx >> 13;
    int jb  = col >> 8, h = col & 255;
    int j   = jb + 1;
    float v;
    if (r < H_) {
        v = g_Pows[(size_t)j * (H_ * H_) + r * H_ + h];
    } else {
        int k = ((r - H_) >> 3) + 1;
        int i = (r - H_) & 7;
        int p = j - k;
        v = (p >= 0) ? g_Mstack[((L_ - 1 - p) * I_ + i) * H_ + h] : 0.f;
    }
    split_tf32(v, g_Ghi[idx], g_Glo[idx]);
}

// ---- Zend[c] = Xwin_c @ Mstack ----
__global__ void k_zend(const float* __restrict__ x) {
    const int c = blockIdx.z;
    __shared__ float as[32][33], bs[32][33];
    const int tx = threadIdx.x & 31;
    const int ty = threadIdx.x >> 5;
    const int row0 = blockIdx.y * 32, col0 = blockIdx.x * 32;
    float acc[4] = {0.f, 0.f, 0.f, 0.f};
    for (int k0 = 0; k0 < H_; k0 += 32) {
#pragma unroll
        for (int e = 0; e < 4; e++) {
            int r = ty + e * 8;
            as[r][tx] = x[(size_t)(row0 + r) * (T_ * I_) + c * (L_ * I_) + k0 + tx];
            bs[r][tx] = g_Mstack[(size_t)(k0 + r) * H_ + col0 + tx];
        }
        __syncthreads();
#pragma unroll
        for (int kq = 0; kq < 32; kq++) {
            float bv = bs[kq][tx];
#pragma unroll
            for (int e = 0; e < 4; e++) acc[e] += as[ty + e * 8][kq] * bv;
        }
        __syncthreads();
    }
#pragma unroll
    for (int e = 0; e < 4; e++)
        g_Zend[(size_t)c * BH + (size_t)(row0 + ty + e * 8) * H_ + col0 + tx] = acc[e];
}

// ---- carry: Hstart[c+1] = Hstart[c] @ A^32 + Zend[c] ----
__global__ void __launch_bounds__(256, 1) k_carry(const float* __restrict__ h0) {
    __shared__ float hb[2][4 * H_];
    const float* P32 = g_Pows + (size_t)32 * (H_ * H_);
    const int r0   = blockIdx.x * 4;
    const int tau  = threadIdx.x;
    const int rowg = tau >> 6;
    const int lg   = tau & 63;
    const int c0   = lg * 4;
#pragma unroll
    for (int e = 0; e < 4; e++) {
        float v = h0[tau];
        hb[0][e * H_ + tau] = v;
        g_Hstart[(size_t)(r0 + e) * H_ + tau] = v;
    }
    __syncthreads();
    int p = 0;
    for (int c = 0; c < C_ - 1; c++) {
        unsigned long long acc[2];
        const unsigned long long* zs = (const unsigned long long*)
            (g_Zend + (size_t)c * BH + (size_t)(r0 + rowg) * H_ + c0);
        acc[0] = zs[0]; acc[1] = zs[1];
        const float* zr = hb[p] + rowg * H_;
#pragma unroll 4
        for (int h = 0; h < H_; h++) {
            ulonglong2 aa = *(const ulonglong2*)(P32 + h * H_ + c0);
            unsigned long long zz = pack2(zr[h]);
            fma2(acc[0], zz, aa.x);
            fma2(acc[1], zz, aa.y);
        }
        unsigned long long* w = (unsigned long long*)(hb[p ^ 1] + rowg * H_ + c0);
        w[0] = acc[0]; w[1] = acc[1];
        unsigned long long* g = (unsigned long long*)
            (g_Hstart + (size_t)(c + 1) * BH + (size_t)(r0 + rowg) * H_ + c0);
        g[0] = acc[0]; g[1] = acc[1];
        __syncthreads();
        p ^= 1;
    }
}

// ---- build U (8192 x 512) split to tf32 hi/lo ----
__global__ void k_buildU(const float* __restrict__ x) {
    size_t idx = (size_t)blockIdx.x * 256 + threadIdx.x;    // 4M
    int kcol = (int)(idx & (KU - 1));
    int row  = (int)(idx >> 9);
    int c = row >> 8, b = row & 255;
    float v = (kcol < H_)
        ? g_Hstart[(size_t)c * BH + (size_t)b * H_ + kcol]
        : x[((size_t)b * T_ + c * L_) * I_ + (kcol - H_)];
    split_tf32(v, g_Uhi[idx], g_Ulo[idx]);
}

// ---- the big GEMM: out(perm) = U @ G via tf32 mma, 2-way split (3 products) --
// CTA tile 128x128, K up to 512 (triangular skip), 8 warps (4M x 2N),
// warp tile 32x64. Smem padded to kill LDS bank conflicts.
__global__ void __launch_bounds__(256, 2) k_gemm(float* __restrict__ out) {
    extern __shared__ uint32_t sm[];
    uint32_t* Ah = sm;                  // [128][40]
    uint32_t* Al = sm + 5120;
    uint32_t* Bh = sm + 10240;          // [32][136]
    uint32_t* Bl = sm + 14592;          // total 18944 u32 = 75776 B

    const int bx = blockIdx.x;          // N block (128 cols)
    const int by = blockIdx.y;          // M block (128 rows)
    const int jb = bx >> 1;             // j-block 0..31
    const int kmax = H_ + 8 * (jb + 1); // triangular K extent
    const int ntiles = (kmax + 31) >> 5;
    const int tid  = threadIdx.x;
    const int wid  = tid >> 5, lane = tid & 31;
    const int wm   = (wid >> 1) * 32;   // warp M offset
    const int wn   = (wid & 1) * 64;    // warp N offset
    const int lq   = lane >> 2;         // 0..7
    const int lr   = lane & 3;          // 0..3

    float c[2][8][4];
#pragma unroll
    for (int mf = 0; mf < 2; mf++)
#pragma unroll
        for (int nf = 0; nf < 8; nf++)
#pragma unroll
            for (int e = 0; e < 4; e++) c[mf][nf][e] = 0.f;

    for (int kt = 0; kt < ntiles; kt++) {
        // stage A tile (U rows by*128..+128, cols kt*32..+32)
        {
            int r  = tid >> 1;
            int c0 = (tid & 1) * 16;
            const uint4* ph = (const uint4*)
                (g_Uhi + (size_t)(by * 128 + r) * KU + kt * 32 + c0);
            const uint4* pl = (const uint4*)
                (g_Ulo + (size_t)(by * 128 + r) * KU + kt * 32 + c0);
#pragma unroll
            for (int e = 0; e < 4; e++) {
                *(uint4*)(Ah + r * 40 + c0 + 4 * e) = ph[e];
                *(uint4*)(Al + r * 40 + c0 + 4 * e) = pl[e];
            }
        }
        // stage B tile (G rows kt*32..+32, cols bx*128..+128)
        {
            int r  = tid >> 3;
            int c0 = (tid & 7) * 16;
            const uint4* ph = (const uint4*)
                (g_Ghi + (size_t)(kt * 32 + r) * NW + bx * 128 + c0);
            const uint4* pl = (const uint4*)
                (g_Glo + (size_t)(kt * 32 + r) * NW + bx * 128 + c0);
#pragma unroll
            for (int e = 0; e < 4; e++) {
                *(uint4*)(Bh + r * 136 + c0 + 4 * e) = ph[e];
                *(uint4*)(Bl + r * 136 + c0 + 4 * e) = pl[e];
            }
        }
        __syncthreads();

#pragma unroll
        for (int k8 = 0; k8 < 4; k8++) {
            const int kb = k8 * 8;
            uint32_t ah[2][4], al[2][4];
            const int ar = wm + lq;
            const int ac = kb + lr;
#pragma unroll
            for (int mf = 0; mf < 2; mf++) {
                int rr = ar + mf * 16;
                ah[mf][0] = Ah[rr * 40 + ac];
                ah[mf][1] = Ah[(rr + 8) * 40 + ac];
                ah[mf][2] = Ah[rr * 40 + ac + 4];
                ah[mf][3] = Ah[(rr + 8) * 40 + ac + 4];
                al[mf][0] = Al[rr * 40 + ac];
                al[mf][1] = Al[(rr + 8) * 40 + ac];
                al[mf][2] = Al[rr * 40 + ac + 4];
                al[mf][3] = Al[(rr + 8) * 40 + ac + 4];
            }
#pragma unroll
            for (int nf = 0; nf < 8; nf++) {
                const int bc = wn + nf * 8 + lq;
                const int br = kb + lr;
                uint32_t bh0 = Bh[br * 136 + bc];
                uint32_t bh1 = Bh[(br + 4) * 136 + bc];
                uint32_t bl0 = Bl[br * 136 + bc];
                uint32_t bl1 = Bl[(br + 4) * 136 + bc];
#pragma unroll
                for (int mf = 0; mf < 2; mf++) {
                    mma_tf32(c[mf][nf], ah[mf], bh0, bh1);
                    mma_tf32(c[mf][nf], ah[mf], bl0, bl1);
                    mma_tf32(c[mf][nf], al[mf], bh0, bh1);
                }
            }
        }
        __syncthreads();
    }

    // epilogue: scatter to out. Chunk = by>>1, t = chunk*32 + jb + 1.
    const int t  = (by >> 1) * L_ + jb + 1;
    const int b0 = (by & 1) * 128 + wm + lq;
    const int h0 = (bx & 1) * 128 + wn + 2 * lr;
#pragma unroll
    for (int mf = 0; mf < 2; mf++) {
#pragma unroll
        for (int nf = 0; nf < 8; nf++) {
            int bb = b0 + mf * 16;
            int hh = h0 + nf * 8;
            float* o1 = out + ((size_t)t * B_ + bb) * H_ + hh;
            float* o2 = out + ((size_t)t * B_ + bb + 8) * H_ + hh;
            __stcs((float2*)o1, make_float2(c[mf][nf][0], c[mf][nf][1]));
            __stcs((float2*)o2, make_float2(c[mf][nf][2], c[mf][nf][3]));
        }
    }
}

// ---------------- launch ----------------
extern "C" void kernel_launch(void* const* d_in, const int* in_sizes, int n_in,
                              void* d_out, int out_size) {
    (void)in_sizes; (void)n_in; (void)out_size;
    const float* x  = (const float*)d_in[0];
    const float* Wh = (const float*)d_in[1];
    const float* Wx = (const float*)d_in[2];
    const float* h0 = (const float*)d_in[3];
    float* out = (float*)d_out;

    const int gemm_smem = 18944 * 4;   // 75776 B
    cudaFuncSetAttribute(k_gemm, cudaFuncAttributeMaxDynamicSharedMemorySize,
                         gemm_smem);

    k_prep<<<264, 256>>>(Wh, Wx);                       // 0
    k_pow<<<dim3(8, 8, 1),  256>>>(0);                  // 1  A^2
    k_pow<<<dim3(8, 8, 2),  256>>>(1);                  // 2  A^3..4
    k_pow<<<dim3(8, 8, 4),  256>>>(2);                  // 3  A^5..8 (PROFILED)
    k_pow<<<dim3(8, 8, 8),  256>>>(3);                  // 4  A^9..16
    k_pow<<<dim3(8, 8, 16), 256>>>(4);                  // 5  A^17..32
    k_vstage<<<1,  256>>>(0);                           // 6  V_1
    k_vstage<<<2,  256>>>(1);                           // 7  V_2..3
    k_vstage<<<4,  256>>>(2);                           // 8  V_4..7
    k_vstage<<<8,  256>>>(3);                           // 9  V_8..15
    k_vstage<<<16, 256>>>(4);                           // 10 V_16..31
    k_buildG<<<(KU * NW) / 256, 256>>>();               // 11
    k_zend<<<dim3(8, 8, 32), 256>>>(x);                 // 12
    k_carry<<<B_ / 4, 256>>>(h0);                       // 13
    k_buildU<<<(8192 * KU) / 256, 256>>>(x);            // 14
    k_out0<<<256, 256>>>(out, h0);                      // 15
    k_gemm<<<dim3(64, 64), 256, gemm_smem>>>(out);      // 16
}

// round 17
// speedup vs baseline: 1.6371x; 1.6371x over previous
#include <cuda_runtime.h>
#include <cstdint>
#include <cstddef>

// Problem constants
#define B_  256
#define T_  1024
#define I_  8
#define H_  256
#define L_  32          // steps per chunk
#define C_  32          // number of chunks
#define BH  (B_*H_)
#define KU  512         // U width = H + L*I
#define NW  8192        // out-cols = L*H (32*256)
#define KUP (KU/2)      // packed K u32 count = 256

// ---------------- device scratch (no allocations allowed) ----------------
__device__ float    g_Pows[33 * H_ * H_];     // Pows[j] = (Wh^T)^j, j=1..32
__device__ float    g_Mstack[H_ * H_];        // row block (31-p)*8 = Wx^T A^p
__device__ uint32_t g_Gph[KUP * NW];          // G packed bf16x2 (hi), [256][8192]
__device__ uint32_t g_Gpl[KUP * NW];          // (lo)
__device__ uint32_t g_Uph[(size_t)8192 * KUP];// U packed bf16x2 (hi), [8192][256]
__device__ uint32_t g_Upl[(size_t)8192 * KUP];// (lo)
__device__ float    g_Zend[(size_t)C_ * BH];
__device__ float    g_Hstart[(size_t)C_ * BH];

// ---------------- helpers ----------------
__device__ __forceinline__ unsigned long long pack2(float v) {
    unsigned long long r;
    asm("mov.b64 %0, {%1, %1};" : "=l"(r) : "f"(v));
    return r;
}
__device__ __forceinline__ void fma2(unsigned long long& d,
                                     unsigned long long a,
                                     unsigned long long b) {
    asm("fma.rn.f32x2 %0, %1, %2, %0;" : "+l"(d) : "l"(a), "l"(b));
}
// split (v0,v1) into bf16 hi/lo pairs packed into u32 (v0 in low half)
__device__ __forceinline__ uint32_t bfsplit2(float v0, float v1, uint32_t& lo) {
    unsigned short h0, h1, l0, l1;
    asm("cvt.rn.bf16.f32 %0, %1;" : "=h"(h0) : "f"(v0));
    asm("cvt.rn.bf16.f32 %0, %1;" : "=h"(h1) : "f"(v1));
    float r0 = v0 - __uint_as_float(((uint32_t)h0) << 16);
    float r1 = v1 - __uint_as_float(((uint32_t)h1) << 16);
    asm("cvt.rn.bf16.f32 %0, %1;" : "=h"(l0) : "f"(r0));
    asm("cvt.rn.bf16.f32 %0, %1;" : "=h"(l1) : "f"(r1));
    lo = (uint32_t)l0 | ((uint32_t)l1 << 16);
    return (uint32_t)h0 | ((uint32_t)h1 << 16);
}
__device__ __forceinline__ void mma_bf16(float (&d)[4], const uint32_t (&a)[4],
                                         uint32_t b0, uint32_t b1) {
    asm volatile(
        "mma.sync.aligned.m16n8k16.row.col.f32.bf16.bf16.f32 "
        "{%0,%1,%2,%3}, {%4,%5,%6,%7}, {%8,%9}, {%0,%1,%2,%3};"
        : "+f"(d[0]), "+f"(d[1]), "+f"(d[2]), "+f"(d[3])
        : "r"(a[0]), "r"(a[1]), "r"(a[2]), "r"(a[3]), "r"(b0), "r"(b1));
}

// ---------------- out[0] = broadcast h0 ----------------
__global__ void k_out0(float* __restrict__ out, const float* __restrict__ h0) {
    int idx = blockIdx.x * 256 + threadIdx.x;
    out[idx] = h0[idx & (H_ - 1)];
}

// ---- seed Pows[1] = Wh^T and Mstack V_0 = Wx^T ----
__global__ void k_prep(const float* __restrict__ Wh, const float* __restrict__ Wx) {
    int idx = blockIdx.x * 256 + threadIdx.x;       // 67584
    if (idx < H_ * H_) {
        int h = idx >> 8, c = idx & 255;
        g_Pows[H_ * H_ + idx] = Wh[c * H_ + h];     // (Wh^T)[h][c]
    } else if (idx < H_ * H_ + I_ * H_) {
        int r = idx - H_ * H_;
        int i = r >> 8, c = r & 255;
        g_Mstack[((L_ - 1) * I_ + i) * H_ + c] = Wx[c * I_ + i];
    }
}

// ---- power doubling: stage m: for kk=1..2^m: Pows[kk+2^m] = Pows[kk]@Pows[2^m]
__global__ void k_pow(int stage) {
    const int nk = 1 << stage;
    const int kk = blockIdx.z + 1;                  // 1..nk
    const float* src  = g_Pows + (size_t)kk * (H_ * H_);
    const float* mult = g_Pows + (size_t)nk * (H_ * H_);
    float* dst        = g_Pows + (size_t)(kk + nk) * (H_ * H_);
    __shared__ float as[32][33], bs[32][33];
    const int tx = threadIdx.x & 31;
    const int ty = threadIdx.x >> 5;
    const int row0 = blockIdx.y * 32, col0 = blockIdx.x * 32;
    float acc[4] = {0.f, 0.f, 0.f, 0.f};
    for (int k0 = 0; k0 < H_; k0 += 32) {
#pragma unroll
        for (int e = 0; e < 4; e++) {
            int r = ty + e * 8;
            as[r][tx] = src[(size_t)(row0 + r) * H_ + k0 + tx];
            bs[r][tx] = mult[(size_t)(k0 + r) * H_ + col0 + tx];
        }
        __syncthreads();
#pragma unroll
        for (int kq = 0; kq < 32; kq++) {
            float bv = bs[kq][tx];
#pragma unroll
            for (int e = 0; e < 4; e++) acc[e] += as[ty + e * 8][kq] * bv;
        }
        __syncthreads();
    }
#pragma unroll
    for (int e = 0; e < 4; e++)
        dst[(size_t)(row0 + ty + e * 8) * H_ + col0 + tx] = acc[e];
}

// ---- Mstack doubling: stage m: V_{k+2^m} = V_k @ Pows[2^m], k=0..2^m-1 ------
__global__ void __launch_bounds__(256, 1) k_vstage(int stage) {
    const int nk = 1 << stage;
    const float* P = g_Pows + (size_t)nk * (H_ * H_);
    const int k = blockIdx.x;
    const int c = threadIdx.x;
    __shared__ float V[I_][H_];
    const float* src = g_Mstack + (size_t)((L_ - 1 - k) * I_) * H_;
#pragma unroll
    for (int i = 0; i < I_; i++) V[i][c] = src[i * H_ + c];
    __syncthreads();
    float acc[I_] = {0.f, 0.f, 0.f, 0.f, 0.f, 0.f, 0.f, 0.f};
#pragma unroll 8
    for (int h = 0; h < H_; h++) {
        float a = P[h * H_ + c];
#pragma unroll
        for (int i = 0; i < I_; i++) acc[i] += V[i][h] * a;
    }
    float* dst = g_Mstack + (size_t)((L_ - 1 - k - nk) * I_) * H_;
#pragma unroll
    for (int i = 0; i < I_; i++) dst[i * H_ + c] = acc[i];
}

// ---- G value at (row r, col) ----
__device__ __forceinline__ float gval(int r, int col) {
    int jb = col >> 8, h = col & 255, j = jb + 1;
    if (r < H_) return g_Pows[(size_t)j * (H_ * H_) + r * H_ + h];
    int k = ((r - H_) >> 3) + 1;
    int i = (r - H_) & 7;
    int p = j - k;
    return (p >= 0) ? g_Mstack[((L_ - 1 - p) * I_ + i) * H_ + h] : 0.f;
}

// ---- build G packed: Gp[kr][col] = bf16x2{G[2kr][col], G[2kr+1][col]} ----
__global__ void k_buildG() {
    int idx = blockIdx.x * 256 + threadIdx.x;       // 2M
    int col = idx & (NW - 1);
    int kr  = idx >> 13;
    float v0 = gval(2 * kr, col);
    float v1 = gval(2 * kr + 1, col);
    uint32_t lo;
    uint32_t hi = bfsplit2(v0, v1, lo);
    g_Gph[idx] = hi;
    g_Gpl[idx] = lo;
}

// ---- Zend[c] = Xwin_c @ Mstack ----
__global__ void k_zend(const float* __restrict__ x) {
    const int c = blockIdx.z;
    __shared__ float as[32][33], bs[32][33];
    const int tx = threadIdx.x & 31;
    const int ty = threadIdx.x >> 5;
    const int row0 = blockIdx.y * 32, col0 = blockIdx.x * 32;
    float acc[4] = {0.f, 0.f, 0.f, 0.f};
    for (int k0 = 0; k0 < H_; k0 += 32) {
#pragma unroll
        for (int e = 0; e < 4; e++) {
            int r = ty + e * 8;
            as[r][tx] = x[(size_t)(row0 + r) * (T_ * I_) + c * (L_ * I_) + k0 + tx];
            bs[r][tx] = g_Mstack[(size_t)(k0 + r) * H_ + col0 + tx];
        }
        __syncthreads();
#pragma unroll
        for (int kq = 0; kq < 32; kq++) {
            float bv = bs[kq][tx];
#pragma unroll
            for (int e = 0; e < 4; e++) acc[e] += as[ty + e * 8][kq] * bv;
        }
        __syncthreads();
    }
#pragma unroll
    for (int e = 0; e < 4; e++)
        g_Zend[(size_t)c * BH + (size_t)(row0 + ty + e * 8) * H_ + col0 + tx] = acc[e];
}

// ---- carry: Hstart[c+1] = Hstart[c] @ A^32 + Zend[c] ----
__global__ void __launch_bounds__(256, 1) k_carry(const float* __restrict__ h0) {
    __shared__ float hb[2][4 * H_];
    const float* P32 = g_Pows + (size_t)32 * (H_ * H_);
    const int r0   = blockIdx.x * 4;
    const int tau  = threadIdx.x;
    const int rowg = tau >> 6;
    const int lg   = tau & 63;
    const int c0   = lg * 4;
#pragma unroll
    for (int e = 0; e < 4; e++) {
        float v = h0[tau];
        hb[0][e * H_ + tau] = v;
        g_Hstart[(size_t)(r0 + e) * H_ + tau] = v;
    }
    __syncthreads();
    int p = 0;
    for (int c = 0; c < C_ - 1; c++) {
        unsigned long long acc[2];
        const unsigned long long* zs = (const unsigned long long*)
            (g_Zend + (size_t)c * BH + (size_t)(r0 + rowg) * H_ + c0);
        acc[0] = zs[0]; acc[1] = zs[1];
        const float* zr = hb[p] + rowg * H_;
#pragma unroll 4
        for (int h = 0; h < H_; h++) {
            ulonglong2 aa = *(const ulonglong2*)(P32 + h * H_ + c0);
            unsigned long long zz = pack2(zr[h]);
            fma2(acc[0], zz, aa.x);
            fma2(acc[1], zz, aa.y);
        }
        unsigned long long* w = (unsigned long long*)(hb[p ^ 1] + rowg * H_ + c0);
        w[0] = acc[0]; w[1] = acc[1];
        unsigned long long* g = (unsigned long long*)
            (g_Hstart + (size_t)(c + 1) * BH + (size_t)(r0 + rowg) * H_ + c0);
        g[0] = acc[0]; g[1] = acc[1];
        __syncthreads();
        p ^= 1;
    }
}

// ---- build U packed: Up[row][kq] = bf16x2{U[row][2kq], U[row][2kq+1]} ----
__global__ void k_buildU(const float* __restrict__ x) {
    int idx = blockIdx.x * 256 + threadIdx.x;       // 2M
    int kq  = idx & (KUP - 1);
    int row = idx >> 8;
    int c = row >> 8, b = row & 255;
    float v0, v1;
    if (kq < 128) {
        const float* hs = g_Hstart + (size_t)c * BH + (size_t)b * H_;
        v0 = hs[2 * kq];
        v1 = hs[2 * kq + 1];
    } else {
        const float* xb = x + ((size_t)b * T_ + c * L_) * I_;
        v0 = xb[2 * kq - H_];
        v1 = xb[2 * kq + 1 - H_];
    }
    uint32_t lo;
    uint32_t hi = bfsplit2(v0, v1, lo);
    g_Uph[(size_t)row * KUP + kq] = hi;
    g_Upl[(size_t)row * KUP + kq] = lo;
}

// ---- the big GEMM: out(perm) = U @ G via bf16x2 mma (3 products) ----
// CTA tile 128x128, triangular K skip, 8 warps (4M x 2N), warp tile 32x64.
// Smem: A [128][20] u32 (hi+lo), B [16][136] u32 (hi+lo) = 37888 B.
__global__ void __launch_bounds__(256, 2) k_gemm(float* __restrict__ out) {
    extern __shared__ uint32_t sm[];
    uint32_t* Ah = sm;                  // 128*20 = 2560
    uint32_t* Al = sm + 2560;
    uint32_t* Bh = sm + 5120;           // 16*136 = 2176
    uint32_t* Bl = sm + 7296;           // total 9472 u32

    const int bx = blockIdx.x;          // N block (128 cols)
    const int by = blockIdx.y;          // M block (128 rows)
    const int jb = bx >> 1;             // j-block 0..31
    const int kmax = H_ + 8 * (jb + 1); // triangular K extent (elements)
    const int ntiles = (kmax + 31) >> 5;
    const int tid  = threadIdx.x;
    const int wid  = tid >> 5, lane = tid & 31;
    const int wm   = (wid >> 1) * 32;   // warp M offset
    const int wn   = (wid & 1) * 64;    // warp N offset
    const int lq   = lane >> 2;         // 0..7
    const int lr   = lane & 3;          // 0..3

    float c[2][8][4];
#pragma unroll
    for (int mf = 0; mf < 2; mf++)
#pragma unroll
        for (int nf = 0; nf < 8; nf++)
#pragma unroll
            for (int e = 0; e < 4; e++) c[mf][nf][e] = 0.f;

    for (int kt = 0; kt < ntiles; kt++) {
        // stage A tile: U rows by*128..+128, packed cols kt*16..+16
        {
            int r  = tid >> 1;
            int cp = (tid & 1) * 8;
            const uint4* ph = (const uint4*)
                (g_Uph + (size_t)(by * 128 + r) * KUP + kt * 16 + cp);
            const uint4* pl = (const uint4*)
                (g_Upl + (size_t)(by * 128 + r) * KUP + kt * 16 + cp);
            *(uint4*)(Ah + r * 20 + cp)     = ph[0];
            *(uint4*)(Ah + r * 20 + cp + 4) = ph[1];
            *(uint4*)(Al + r * 20 + cp)     = pl[0];
            *(uint4*)(Al + r * 20 + cp + 4) = pl[1];
        }
        // stage B tile: G packed rows kt*16..+16, cols bx*128..+128
        {
            int kr = tid >> 4;
            int c0 = (tid & 15) * 8;
            const uint4* qh = (const uint4*)
                (g_Gph + (size_t)(kt * 16 + kr) * NW + bx * 128 + c0);
            const uint4* ql = (const uint4*)
                (g_Gpl + (size_t)(kt * 16 + kr) * NW + bx * 128 + c0);
            *(uint4*)(Bh + kr * 136 + c0)     = qh[0];
            *(uint4*)(Bh + kr * 136 + c0 + 4) = qh[1];
            *(uint4*)(Bl + kr * 136 + c0)     = ql[0];
            *(uint4*)(Bl + kr * 136 + c0 + 4) = ql[1];
        }
        __syncthreads();

#pragma unroll
        for (int k16 = 0; k16 < 2; k16++) {
            const int kb = k16 * 8;            // u32 offset within tile
            uint32_t ah[2][4], al[2][4];
#pragma unroll
            for (int mf = 0; mf < 2; mf++) {
                int rr = wm + lq + mf * 16;
                ah[mf][0] = Ah[rr * 20 + kb + lr];
                ah[mf][1] = Ah[(rr + 8) * 20 + kb + lr];
                ah[mf][2] = Ah[rr * 20 + kb + lr + 4];
                ah[mf][3] = Ah[(rr + 8) * 20 + kb + lr + 4];
                al[mf][0] = Al[rr * 20 + kb + lr];
                al[mf][1] = Al[(rr + 8) * 20 + kb + lr];
                al[mf][2] = Al[rr * 20 + kb + lr + 4];
                al[mf][3] = Al[(rr + 8) * 20 + kb + lr + 4];
            }
#pragma unroll
            for (int nf = 0; nf < 8; nf++) {
                const int bc = wn + nf * 8 + lq;
                uint32_t bh0 = Bh[(kb + lr) * 136 + bc];
                uint32_t bh1 = Bh[(kb + lr + 4) * 136 + bc];
                uint32_t bl0 = Bl[(kb + lr) * 136 + bc];
                uint32_t bl1 = Bl[(kb + lr + 4) * 136 + bc];
#pragma unroll
                for (int mf = 0; mf < 2; mf++) {
                    mma_bf16(c[mf][nf], ah[mf], bh0, bh1);
                    mma_bf16(c[mf][nf], ah[mf], bl0, bl1);
                    mma_bf16(c[mf][nf], al[mf], bh0, bh1);
                }
            }
        }
        __syncthreads();
    }

    // epilogue (validated in R16): t = chunk*32 + jb + 1
    const int t  = (by >> 1) * L_ + jb + 1;
    const int b0 = (by & 1) * 128 + wm + lq;
    const int h0 = (bx & 1) * 128 + wn + 2 * lr;
#pragma unroll
    for (int mf = 0; mf < 2; mf++) {
#pragma unroll
        for (int nf = 0; nf < 8; nf++) {
            int bb = b0 + mf * 16;
            int hh = h0 + nf * 8;
            float* o1 = out + ((size_t)t * B_ + bb) * H_ + hh;
            float* o2 = out + ((size_t)t * B_ + bb + 8) * H_ + hh;
            __stcs((float2*)o1, make_float2(c[mf][nf][0], c[mf][nf][1]));
            __stcs((float2*)o2, make_float2(c[mf][nf][2], c[mf][nf][3]));
        }
    }
}

// ---------------- launch ----------------
extern "C" void kernel_launch(void* const* d_in, const int* in_sizes, int n_in,
                              void* d_out, int out_size) {
    (void)in_sizes; (void)n_in; (void)out_size;
    const float* x  = (const float*)d_in[0];
    const float* Wh = (const float*)d_in[1];
    const float* Wx = (const float*)d_in[2];
    const float* h0 = (const float*)d_in[3];
    float* out = (float*)d_out;

    const int gemm_smem = 9472 * 4;    // 37888 B
    cudaFuncSetAttribute(k_gemm, cudaFuncAttributeMaxDynamicSharedMemorySize,
                         gemm_smem);

    k_prep<<<264, 256>>>(Wh, Wx);                       // 0
    k_pow<<<dim3(8, 8, 1),  256>>>(0);                  // 1  A^2
    k_pow<<<dim3(8, 8, 2),  256>>>(1);                  // 2  A^3..4
    k_pow<<<dim3(8, 8, 4),  256>>>(2);                  // 3  A^5..8
    k_pow<<<dim3(8, 8, 8),  256>>>(3);                  // 4  A^9..16
    k_pow<<<dim3(8, 8, 16), 256>>>(4);                  // 5  A^17..32
    k_vstage<<<1,  256>>>(0);                           // 6  V_1
    k_vstage<<<2,  256>>>(1);                           // 7  V_2..3
    k_vstage<<<4,  256>>>(2);                           // 8  V_4..7
    k_vstage<<<8,  256>>>(3);                           // 9  V_8..15
    k_vstage<<<16, 256>>>(4);                           // 10 V_16..31
    k_buildG<<<(KUP * NW) / 256, 256>>>();              // 11
    k_zend<<<dim3(8, 8, 32), 256>>>(x);                 // 12
    k_carry<<<B_ / 4, 256>>>(h0);                       // 13
    k_buildU<<<(8192 * KUP) / 256, 256>>>(x);           // 14
    k_out0<<<256, 256>>>(out, h0);                      // 15
    k_gemm<<<dim3(64, 64), 256, gemm_smem>>>(out);      // 16
}